// round 10
// baseline (speedup 1.0000x reference)
#include <cuda_runtime.h>
#include <cuda_bf16.h>
#include <cstdint>
#include <math.h>

// ---------------------------------------------------------------------------
// Problem constants
// ---------------------------------------------------------------------------
#define BB   4
#define TT   2048
#define CC   1024
#define HH   16
#define HS   64
#define CUT  1024
#define ROWS_FULL (BB*TT)   // 8192
#define ROWS_CUT  (BB*CUT)  // 4096
#define SCALE 0.03125f      // C^-0.5

// ---------------------------------------------------------------------------
// Scratch (device globals; no allocations allowed)
// ---------------------------------------------------------------------------
__device__ float g_h   [ROWS_FULL * CC];
__device__ float g_K   [BB*HH*TT*HS];
__device__ float g_V   [BB*HH*TT*HS];
__device__ float g_Vt  [BB*HH*HS*TT];     // V transposed [bh][d][t]
__device__ float g_Q   [BB*HH*CUT*HS];
__device__ float g_o   [ROWS_CUT * CC];
__device__ float g_res [ROWS_CUT * CC];
__device__ float g_h2  [ROWS_CUT * CC];
__device__ float g_a1  [ROWS_CUT * 4*CC];
__device__ float g_Wqkv[3 * CC * CC];     // [3072, 1024] K-major
__device__ float g_Wp  [CC * CC];
__device__ float g_W1  [4*CC * CC];
__device__ float g_W2  [CC * 4*CC];
__device__ float g_bqkv[3 * CC];

// ---------------------------------------------------------------------------
// Helpers
// ---------------------------------------------------------------------------
__device__ __forceinline__ uint32_t smem_u32(const void* p) {
    uint32_t a;
    asm("{ .reg .u64 t; cvta.to.shared.u64 t, %1; cvt.u32.u64 %0, t; }"
        : "=r"(a) : "l"(p));
    return a;
}
// round fp32 -> tf32 (nearest) so HW tf32 truncation is a no-op
__device__ __forceinline__ float rtf32(float x) {
    uint32_t u = __float_as_uint(x);
    u = (u + 0x1000u) & 0xFFFFE000u;
    return __uint_as_float(u);
}
__device__ __forceinline__ float gelu_exact(float x) {
    return 0.5f * x * (1.0f + erff(x * 0.70710678118654752440f));
}

#define CP_ASYNC16(dst, src) \
    asm volatile("cp.async.cg.shared.global [%0], [%1], 16;" :: "r"(dst), "l"(src))
#define CP_COMMIT() asm volatile("cp.async.commit_group;")
#define CP_WAIT(n)  asm volatile("cp.async.wait_group %0;" :: "n"(n))

#define LDSM_X4(r0, r1, r2, r3, a) \
    asm volatile("ldmatrix.sync.aligned.m8n8.x4.shared.b16 {%0,%1,%2,%3}, [%4];" \
        : "=r"(r0), "=r"(r1), "=r"(r2), "=r"(r3) : "r"(a))

__device__ __forceinline__ void mma_tf32(float* c, const uint32_t* a, const uint32_t* b) {
    asm volatile(
        "mma.sync.aligned.m16n8k8.row.col.f32.tf32.tf32.f32 "
        "{%0,%1,%2,%3}, {%4,%5,%6,%7}, {%8,%9}, {%0,%1,%2,%3};"
        : "+f"(c[0]), "+f"(c[1]), "+f"(c[2]), "+f"(c[3])
        : "r"(a[0]), "r"(a[1]), "r"(a[2]), "r"(a[3]), "r"(b[0]), "r"(b[1]));
}

// ---------------------------------------------------------------------------
// Transpose + round: dst[n*K+k] = rtf32(src[k*N+n])
// ---------------------------------------------------------------------------
__global__ void tr_kernel(const float* __restrict__ src, float* __restrict__ dst,
                          int K, int N)
{
    __shared__ float t[32][33];
    int k0 = blockIdx.y * 32, n0 = blockIdx.x * 32;
    int tx = threadIdx.x, ty = threadIdx.y;      // 32 x 8
    #pragma unroll
    for (int i = 0; i < 32; i += 8)
        t[ty + i][tx] = src[(size_t)(k0 + ty + i) * N + n0 + tx];
    __syncthreads();
    #pragma unroll
    for (int i = 0; i < 32; i += 8)
        dst[(size_t)(n0 + ty + i) * K + k0 + tx] = rtf32(t[tx][ty + i]);
}

// QKV: [H,C,HS] x3 -> [3072, 1024] K-major; batch z: w=z/16, h=z%16
__global__ void qkv_tr_kernel(const float* __restrict__ Wq,
                              const float* __restrict__ Wk,
                              const float* __restrict__ Wv,
                              float* __restrict__ dst)
{
    __shared__ float t[32][33];
    int z = blockIdx.z, w = z >> 4, h = z & 15;
    const float* W = (w == 0) ? Wq : ((w == 1) ? Wk : Wv);
    const float* src = W + (size_t)h * CC * HS;
    float* d = dst + (size_t)w * CC * CC + (size_t)(h * HS) * CC;
    int k0 = blockIdx.y * 32, n0 = blockIdx.x * 32;
    int tx = threadIdx.x, ty = threadIdx.y;
    #pragma unroll
    for (int i = 0; i < 32; i += 8)
        t[ty + i][tx] = src[(size_t)(k0 + ty + i) * HS + n0 + tx];
    __syncthreads();
    #pragma unroll
    for (int i = 0; i < 32; i += 8)
        d[(size_t)(n0 + ty + i) * CC + k0 + tx] = rtf32(t[tx][ty + i]);
}

__global__ void bias_pack_kernel(const float* __restrict__ bq,
                                 const float* __restrict__ bk,
                                 const float* __restrict__ bv,
                                 float* __restrict__ out)
{
    int w = blockIdx.x, i = threadIdx.x;
    const float* b = (w == 0) ? bq : ((w == 1) ? bk : bv);
    out[w * CC + i] = b[i];
}

// V [bh][t][d] -> Vt [bh][d][t]
__global__ void vtr_kernel(const float* __restrict__ V, float* __restrict__ Vt)
{
    __shared__ float t[32][33];
    int bh = blockIdx.z;
    int t0 = blockIdx.x * 32, d0 = blockIdx.y * 32;
    const float* src = V + (size_t)bh * TT * HS;
    float* dst = Vt + (size_t)bh * HS * TT;
    int tx = threadIdx.x, ty = threadIdx.y;
    #pragma unroll
    for (int i = 0; i < 32; i += 8)
        t[ty + i][tx] = src[(size_t)(t0 + ty + i) * HS + d0 + tx];
    __syncthreads();
    #pragma unroll
    for (int i = 0; i < 32; i += 8)
        dst[(size_t)(d0 + ty + i) * TT + t0 + tx] = t[tx][ty + i];
}

// ---------------------------------------------------------------------------
// LayerNorm (rounds output to tf32 — it only feeds GEMMs)
// ---------------------------------------------------------------------------
__global__ void ln_kernel(const float* __restrict__ in, float* __restrict__ out,
                          const float* __restrict__ w, const float* __restrict__ b)
{
    int row = blockIdx.x;
    int tid = threadIdx.x;
    const float4 x4 = ((const float4*)(in + (size_t)row * CC))[tid];
    float s  = x4.x + x4.y + x4.z + x4.w;
    float s2 = x4.x*x4.x + x4.y*x4.y + x4.z*x4.z + x4.w*x4.w;
    #pragma unroll
    for (int off = 16; off > 0; off >>= 1) {
        s  += __shfl_xor_sync(0xffffffffu, s,  off);
        s2 += __shfl_xor_sync(0xffffffffu, s2, off);
    }
    __shared__ float red[2][8];
    int wid = tid >> 5, lane = tid & 31;
    if (lane == 0) { red[0][wid] = s; red[1][wid] = s2; }
    __syncthreads();
    float ts = 0.f, ts2 = 0.f;
    #pragma unroll
    for (int i = 0; i < 8; i++) { ts += red[0][i]; ts2 += red[1][i]; }
    float mean = ts * (1.0f / CC);
    float var  = ts2 * (1.0f / CC) - mean * mean;
    float rstd = rsqrtf(var + 1e-5f);
    const float4 w4 = ((const float4*)w)[tid];
    const float4 b4 = ((const float4*)b)[tid];
    float4 o4;
    o4.x = rtf32((x4.x - mean) * rstd * w4.x + b4.x);
    o4.y = rtf32((x4.y - mean) * rstd * w4.y + b4.y);
    o4.z = rtf32((x4.z - mean) * rstd * w4.z + b4.z);
    o4.w = rtf32((x4.w - mean) * rstd * w4.w + b4.w);
    ((float4*)(out + (size_t)row * CC))[tid] = o4;
}

// ---------------------------------------------------------------------------
// Tensor-core tf32 GEMM via mma.sync (m16n8k8), persistent-CTA tile loop.
// CTA tile 128x128, BK=32, 256 threads: 8 warps 2(M)x4(N), warp tile 64x32.
// AMAP: 0 identity A rows, 1 = last-CUT rows of [B,T] layout
// EPI:  0 = Q scatter (N=1024, tf32 round)
//       1 = KV scatter (N=2048: cols<1024 -> R1(K), else R2(V), tf32 round)
//       2 = +x residual (row remap) -> C
//       3 = gelu+round -> C
//       4 = +R1 residual -> C
// ---------------------------------------------------------------------------
#define GEMM_SMEM (3 * 8192 * 4)   // 96 KB

template<int AMAP, int EPI>
__global__ void __launch_bounds__(256)
tc_gemm(const float* __restrict__ A, const float* __restrict__ Bt,
        float* __restrict__ C, const float* __restrict__ bias,
        const float* __restrict__ R1, const float* __restrict__ R2,
        int M, int N, int K)
{
    extern __shared__ float sm[];
    __shared__ float sbias[128];

    const int tid  = threadIdx.x;
    const int lane = tid & 31;
    const int warp = tid >> 5;
    const int wm   = warp & 1;
    const int wn   = warp >> 1;

    const uint32_t smb = smem_u32(sm);
    const int nt  = K >> 5;
    const int nbx = N >> 7;
    const int ntile = nbx * (M >> 7);

    int rA[4], rB[2];
    #pragma unroll
    for (int mf = 0; mf < 4; mf++) rA[mf] = wm * 64 + mf * 16 + (lane & 15);
    #pragma unroll
    for (int p = 0; p < 2; p++)
        rB[p] = wn * 32 + p * 16 + (lane & 7) + ((lane >> 4) << 3);
    const int gA_hi = lane >> 4;
    const int gB_hi = (lane >> 3) & 1;

    for (int tile = blockIdx.x; tile < ntile; tile += gridDim.x) {
        const int n0 = (tile % nbx) * 128;
        const int m0 = (tile / nbx) * 128;

        __syncthreads();   // previous tile's epilogue reads of sbias done
        if (tid < 128) sbias[tid] = bias[n0 + tid];

        auto load_tile = [&](int it) {
            const int s = it % 3;
            const uint32_t sa = smb + (uint32_t)s * 32768u;
            const uint32_t sb = sa + 16384u;
            const float* gA = A  + (size_t)it * 32;
            const float* gB = Bt + (size_t)it * 32;
            #pragma unroll
            for (int i = 0; i < 4; i++) {
                int lin = i * 256 + tid;
                int r = lin >> 3;
                int g = lin & 7;
                int row = m0 + r;
                int arow = AMAP ? ((row >> 10) * TT + (TT - CUT) + (row & (CUT-1)))
                                : row;
                uint32_t off = (uint32_t)(r * 32 + ((g ^ (r & 7)) * 4)) * 4u;
                CP_ASYNC16(sa + off, gA + (size_t)arow * K + g * 4);
                CP_ASYNC16(sb + off, gB + (size_t)(n0 + r) * K + g * 4);
            }
            CP_COMMIT();
        };

        float acc[4][4][4];
        #pragma unroll
        for (int i = 0; i < 4; i++)
            #pragma unroll
            for (int j = 0; j < 4; j++)
                #pragma unroll
                for (int k = 0; k < 4; k++) acc[i][j][k] = 0.f;

        load_tile(0);
        if (nt > 1) load_tile(1);

        for (int it = 0; it < nt; ++it) {
            const int s = it % 3;
            if (it < nt - 1) { CP_WAIT(1); } else { CP_WAIT(0); }
            __syncthreads();
            if (it + 2 < nt) load_tile(it + 2);

            const uint32_t sa = smb + (uint32_t)s * 32768u;
            const uint32_t sb = sa + 16384u;

            #pragma unroll
            for (int ks = 0; ks < 4; ks++) {
                uint32_t a[4][4], b[4][2];
                #pragma unroll
                for (int mf = 0; mf < 4; mf++) {
                    int g = (2 * ks + gA_hi) ^ (rA[mf] & 7);
                    uint32_t addr = sa + (uint32_t)(rA[mf] * 32 + g * 4) * 4u;
                    LDSM_X4(a[mf][0], a[mf][1], a[mf][2], a[mf][3], addr);
                }
                #pragma unroll
                for (int p = 0; p < 2; p++) {
                    int g = (2 * ks + gB_hi) ^ (rB[p] & 7);
                    uint32_t addr = sb + (uint32_t)(rB[p] * 32 + g * 4) * 4u;
                    LDSM_X4(b[2*p][0], b[2*p][1], b[2*p+1][0], b[2*p+1][1], addr);
                }
                #pragma unroll
                for (int mf = 0; mf < 4; mf++)
                    #pragma unroll
                    for (int nf = 0; nf < 4; nf++)
                        mma_tf32(acc[mf][nf], a[mf], b[nf]);
            }
        }

        // ---- epilogue ----
        #pragma unroll
        for (int mf = 0; mf < 4; mf++) {
            #pragma unroll
            for (int nf = 0; nf < 4; nf++) {
                int lrow = wm * 64 + mf * 16 + (lane >> 2);
                int lcol = wn * 32 + nf * 8 + 2 * (lane & 3);
                float sb0 = sbias[lcol], sb1 = sbias[lcol + 1];
                #pragma unroll
                for (int rr = 0; rr < 2; rr++) {
                    int gi   = m0 + lrow + rr * 8;
                    int gcol = n0 + lcol;
                    float2 v = make_float2(acc[mf][nf][2*rr]   + sb0,
                                           acc[mf][nf][2*rr+1] + sb1);
                    if (EPI == 0) {
                        v.x = rtf32(v.x); v.y = rtf32(v.y);
                        int h = gcol >> 6, d0 = gcol & 63;
                        int b_ = gi >> 10, s_ = gi & 1023;
                        *(float2*)(C + ((((size_t)b_ * HH + h) * CUT) + s_) * HS + d0) = v;
                    } else if (EPI == 1) {
                        v.x = rtf32(v.x); v.y = rtf32(v.y);
                        int w = gcol >> 10, r = gcol & 1023;
                        int h = r >> 6, d0 = r & 63;
                        int b_ = gi >> 11, t = gi & 2047;
                        float* dst = (w == 0) ? (float*)R1 : (float*)R2;
                        *(float2*)(dst + (((size_t)b_ * HH + h) * TT + t) * HS + d0) = v;
                    } else if (EPI == 2) {
                        int xrow = (gi >> 10) * TT + (TT - CUT) + (gi & 1023);
                        float2 xv = *(const float2*)(R1 + (size_t)xrow * CC + gcol);
                        *(float2*)(C + (size_t)gi * N + gcol) =
                            make_float2(v.x + xv.x, v.y + xv.y);
                    } else if (EPI == 3) {
                        *(float2*)(C + (size_t)gi * N + gcol) =
                            make_float2(rtf32(gelu_exact(v.x)), rtf32(gelu_exact(v.y)));
                    } else {
                        float2 rv = *(const float2*)(R1 + (size_t)gi * N + gcol);
                        *(float2*)(C + (size_t)gi * N + gcol) =
                            make_float2(v.x + rv.x, v.y + rv.y);
                    }
                }
            }
        }
    }
}

// ---------------------------------------------------------------------------
// Tensor-core flash attention (tf32 mma for QK^T and PV).
// Grid (qt=16, bh=64), 128 threads (4 warps x 16 query rows).
// SMEM floats: QsPs[4096] | Ks[2][4096] | Vs[2][4096]  = 80KB
// ---------------------------------------------------------------------------
#define ATT_SMEM (20480 * 4)

__global__ void __launch_bounds__(128)
attn_tc(const float* __restrict__ Qg, const float* __restrict__ Kg,
        const float* __restrict__ Vtg, float* __restrict__ O)
{
    extern __shared__ float smf[];
    const int qt   = blockIdx.x;
    const int bh   = blockIdx.y;
    const int tid  = threadIdx.x;
    const int lane = tid & 31;
    const int warp = tid >> 5;
    const uint32_t sb = smem_u32(smf);
    const uint32_t sQP = sb;

    const float* Qbase = Qg  + ((size_t)bh * CUT + (size_t)qt * 64) * HS;
    const float* Kbase = Kg  + (size_t)bh * TT * HS;
    const float* Vbase = Vtg + (size_t)bh * HS * TT;

    auto swb = [](int r, int g) {
        return (uint32_t)(r * 64 + ((g ^ (r & 7)) * 4)) * 4u;
    };

    #pragma unroll
    for (int it = 0; it < 8; it++) {
        int lin = it * 128 + tid;
        int r = lin >> 4, g = lin & 15;
        CP_ASYNC16(sQP + swb(r, g), Qbase + r * 64 + g * 4);
    }
    CP_COMMIT();

    auto load_kv = [&](int kt, int buf) {
        uint32_t kdst = sb + (uint32_t)(4096 + buf * 4096) * 4u;
        uint32_t vdst = sb + (uint32_t)(12288 + buf * 4096) * 4u;
        const float* ks = Kbase + (size_t)kt * 64 * 64;
        const float* vs = Vbase + (size_t)kt * 64;
        #pragma unroll
        for (int it = 0; it < 8; it++) {
            int lin = it * 128 + tid;
            int r = lin >> 4, g = lin & 15;
            CP_ASYNC16(kdst + swb(r, g), ks + (size_t)r * 64 + g * 4);
            CP_ASYNC16(vdst + swb(r, g), vs + (size_t)r * TT + g * 4);
        }
        CP_COMMIT();
    };

    load_kv(0, 0);
    CP_WAIT(1);
    __syncthreads();

    uint32_t qf[8][4];
    {
        int rA = warp * 16 + (lane & 15);
        #pragma unroll
        for (int ks = 0; ks < 8; ks++) {
            int g = (2 * ks + (lane >> 4)) ^ (rA & 7);
            uint32_t addr = sQP + (uint32_t)(rA * 64 + g * 4) * 4u;
            LDSM_X4(qf[ks][0], qf[ks][1], qf[ks][2], qf[ks][3], addr);
        }
    }

    float m[2] = {-1e30f, -1e30f}, l[2] = {0.f, 0.f};
    float oacc[8][4];
    #pragma unroll
    for (int nf = 0; nf < 8; nf++)
        #pragma unroll
        for (int e = 0; e < 4; e++) oacc[nf][e] = 0.f;

    const int rA_ld  = warp * 16 + (lane & 15);
    const int gA_hi  = lane >> 4;
    const int gB_hi  = (lane >> 3) & 1;
    int rB[4];
    #pragma unroll
    for (int p = 0; p < 4; p++)
        rB[p] = p * 16 + (lane & 7) + ((lane >> 4) << 3);

    const int ktmax = (TT - CUT) / 64 + qt;

    for (int kt = 0; kt <= ktmax; kt++) {
        const int buf = kt & 1;
        __syncthreads();
        if (kt < ktmax) load_kv(kt + 1, buf ^ 1);
        if (kt < ktmax) { CP_WAIT(1); } else { CP_WAIT(0); }
        __syncthreads();

        const uint32_t kB = sb + (uint32_t)(4096 + buf * 4096) * 4u;
        const uint32_t vB = sb + (uint32_t)(12288 + buf * 4096) * 4u;

        float sfr[8][4];
        #pragma unroll
        for (int nf = 0; nf < 8; nf++)
            #pragma unroll
            for (int e = 0; e < 4; e++) sfr[nf][e] = 0.f;

        #pragma unroll
        for (int ks = 0; ks < 8; ks++) {
            uint32_t b[8][2];
            #pragma unroll
            for (int p = 0; p < 4; p++) {
                int g = (2 * ks + gB_hi) ^ (rB[p] & 7);
                uint32_t addr = kB + (uint32_t)(rB[p] * 64 + g * 4) * 4u;
                LDSM_X4(b[2*p][0], b[2*p][1], b[2*p+1][0], b[2*p+1][1], addr);
            }
            #pragma unroll
            for (int nf = 0; nf < 8; nf++)
                mma_tf32(sfr[nf], qf[ks], b[nf]);
        }

        #pragma unroll
        for (int nf = 0; nf < 8; nf++)
            #pragma unroll
            for (int e = 0; e < 4; e++) sfr[nf][e] *= SCALE;

        if (kt == ktmax) {
            int r0 = warp * 16 + (lane >> 2);
            #pragma unroll
            for (int nf = 0; nf < 8; nf++) {
                int c0 = nf * 8 + 2 * (lane & 3);
                if (c0     > r0)     sfr[nf][0] = -1e30f;
                if (c0 + 1 > r0)     sfr[nf][1] = -1e30f;
                if (c0     > r0 + 8) sfr[nf][2] = -1e30f;
                if (c0 + 1 > r0 + 8) sfr[nf][3] = -1e30f;
            }
        }

        float mt[2] = {-1e30f, -1e30f};
        #pragma unroll
        for (int nf = 0; nf < 8; nf++) {
            mt[0] = fmaxf(mt[0], fmaxf(sfr[nf][0], sfr[nf][1]));
            mt[1] = fmaxf(mt[1], fmaxf(sfr[nf][2], sfr[nf][3]));
        }
        #pragma unroll
        for (int i = 0; i < 2; i++) {
            mt[i] = fmaxf(mt[i], __shfl_xor_sync(0xffffffffu, mt[i], 1));
            mt[i] = fmaxf(mt[i], __shfl_xor_sync(0xffffffffu, mt[i], 2));
        }
        float sc[2], rs[2];
        #pragma unroll
        for (int i = 0; i < 2; i++) {
            float mnew = fmaxf(m[i], mt[i]);
            sc[i] = __expf(m[i] - mnew);
            m[i]  = mnew;
            rs[i] = 0.f;
        }
        #pragma unroll
        for (int nf = 0; nf < 8; nf++) {
            sfr[nf][0] = __expf(sfr[nf][0] - m[0]);
            sfr[nf][1] = __expf(sfr[nf][1] - m[0]);
            sfr[nf][2] = __expf(sfr[nf][2] - m[1]);
            sfr[nf][3] = __expf(sfr[nf][3] - m[1]);
            rs[0] += sfr[nf][0] + sfr[nf][1];
            rs[1] += sfr[nf][2] + sfr[nf][3];
        }
        #pragma unroll
        for (int i = 0; i < 2; i++) {
            rs[i] += __shfl_xor_sync(0xffffffffu, rs[i], 1);
            rs[i] += __shfl_xor_sync(0xffffffffu, rs[i], 2);
            l[i] = l[i] * sc[i] + rs[i];
        }
        #pragma unroll
        for (int nf = 0; nf < 8; nf++) {
            oacc[nf][0] *= sc[0]; oacc[nf][1] *= sc[0];
            oacc[nf][2] *= sc[1]; oacc[nf][3] *= sc[1];
        }

        {
            int r0 = warp * 16 + (lane >> 2);
            #pragma unroll
            for (int nf = 0; nf < 8; nf++) {
                int j0 = nf * 8 + 2 * (lane & 3);
                int g = j0 >> 2, o4 = j0 & 3;
                int i1 = r0 * 64 + ((g ^ (r0 & 7)) * 4 + o4);
                int r2 = r0 + 8;
                int i2 = r2 * 64 + ((g ^ (r2 & 7)) * 4 + o4);
                *(float2*)(smf + i1) = make_float2(rtf32(sfr[nf][0]), rtf32(sfr[nf][1]));
                *(float2*)(smf + i2) = make_float2(rtf32(sfr[nf][2]), rtf32(sfr[nf][3]));
            }
        }
        __syncthreads();

        #pragma unroll
        for (int ks = 0; ks < 8; ks++) {
            uint32_t a[4];
            {
                int g = (2 * ks + gA_hi) ^ (rA_ld & 7);
                uint32_t addr = sQP + (uint32_t)(rA_ld * 64 + g * 4) * 4u;
                LDSM_X4(a[0], a[1], a[2], a[3], addr);
            }
            uint32_t b[8][2];
            #pragma unroll
            for (int p = 0; p < 4; p++) {
                int g = (2 * ks + gB_hi) ^ (rB[p] & 7);
                uint32_t addr = vB + (uint32_t)(rB[p] * 64 + g * 4) * 4u;
                LDSM_X4(b[2*p][0], b[2*p][1], b[2*p+1][0], b[2*p+1][1], addr);
            }
            #pragma unroll
            for (int nf = 0; nf < 8; nf++)
                mma_tf32(oacc[nf], a, b[nf]);
        }
    }

    const int b_ = bh >> 4, h_ = bh & 15;
    const int r0 = warp * 16 + (lane >> 2);
    float inv0 = 1.0f / l[0], inv1 = 1.0f / l[1];
    #pragma unroll
    for (int nf = 0; nf < 8; nf++) {
        int j0 = nf * 8 + 2 * (lane & 3);
        size_t a1 = ((size_t)b_ * CUT + qt * 64 + r0) * CC + h_ * HS + j0;
        size_t a2 = ((size_t)b_ * CUT + qt * 64 + r0 + 8) * CC + h_ * HS + j0;
        *(float2*)(O + a1) = make_float2(rtf32(oacc[nf][0] * inv0),
                                         rtf32(oacc[nf][1] * inv0));
        *(float2*)(O + a2) = make_float2(rtf32(oacc[nf][2] * inv1),
                                         rtf32(oacc[nf][3] * inv1));
    }
}

// ---------------------------------------------------------------------------
// Launch
// ---------------------------------------------------------------------------
#define NPERS 296   // 148 SMs x 2 CTAs

extern "C" void kernel_launch(void* const* d_in, const int* in_sizes, int n_in,
                              void* d_out, int out_size)
{
    const float* x      = (const float*)d_in[0];
    const float* ln1_w  = (const float*)d_in[1];
    const float* ln1_b  = (const float*)d_in[2];
    const float* Wq     = (const float*)d_in[3];
    const float* bq     = (const float*)d_in[4];
    const float* Wk     = (const float*)d_in[5];
    const float* bk     = (const float*)d_in[6];
    const float* Wv     = (const float*)d_in[7];
    const float* bv     = (const float*)d_in[8];
    const float* proj_w = (const float*)d_in[9];
    const float* proj_b = (const float*)d_in[10];
    const float* ln2_w  = (const float*)d_in[11];
    const float* ln2_b  = (const float*)d_in[12];
    const float* lin1_w = (const float*)d_in[13];
    const float* lin1_b = (const float*)d_in[14];
    const float* lin2_w = (const float*)d_in[15];
    const float* lin2_b = (const float*)d_in[16];
    float* out = (float*)d_out;

    float *p_h, *p_K, *p_V, *p_Vt, *p_Q, *p_o, *p_res, *p_h2, *p_a1;
    float *p_Wqkv, *p_Wp, *p_W1, *p_W2, *p_bqkv;
    cudaGetSymbolAddress((void**)&p_h,    g_h);
    cudaGetSymbolAddress((void**)&p_K,    g_K);
    cudaGetSymbolAddress((void**)&p_V,    g_V);
    cudaGetSymbolAddress((void**)&p_Vt,   g_Vt);
    cudaGetSymbolAddress((void**)&p_Q,    g_Q);
    cudaGetSymbolAddress((void**)&p_o,    g_o);
    cudaGetSymbolAddress((void**)&p_res,  g_res);
    cudaGetSymbolAddress((void**)&p_h2,   g_h2);
    cudaGetSymbolAddress((void**)&p_a1,   g_a1);
    cudaGetSymbolAddress((void**)&p_Wqkv, g_Wqkv);
    cudaGetSymbolAddress((void**)&p_Wp,   g_Wp);
    cudaGetSymbolAddress((void**)&p_W1,   g_W1);
    cudaGetSymbolAddress((void**)&p_W2,   g_W2);
    cudaGetSymbolAddress((void**)&p_bqkv, g_bqkv);

    static bool once = false;
    if (!once) {
        cudaFuncSetAttribute(attn_tc,
                             cudaFuncAttributeMaxDynamicSharedMemorySize, ATT_SMEM);
        cudaFuncSetAttribute((const void*)tc_gemm<1,0>,
                             cudaFuncAttributeMaxDynamicSharedMemorySize, GEMM_SMEM);
        cudaFuncSetAttribute((const void*)tc_gemm<0,1>,
                             cudaFuncAttributeMaxDynamicSharedMemorySize, GEMM_SMEM);
        cudaFuncSetAttribute((const void*)tc_gemm<0,2>,
                             cudaFuncAttributeMaxDynamicSharedMemorySize, GEMM_SMEM);
        cudaFuncSetAttribute((const void*)tc_gemm<0,3>,
                             cudaFuncAttributeMaxDynamicSharedMemorySize, GEMM_SMEM);
        cudaFuncSetAttribute((const void*)tc_gemm<0,4>,
                             cudaFuncAttributeMaxDynamicSharedMemorySize, GEMM_SMEM);
        once = true;
    }

    // weight repack (transpose + tf32 round) + bias pack + LN1
    qkv_tr_kernel<<<dim3(2, 32, 48), dim3(32, 8)>>>(Wq, Wk, Wv, p_Wqkv);
    tr_kernel<<<dim3(32, 32),  dim3(32, 8)>>>(proj_w, p_Wp, CC, CC);
    tr_kernel<<<dim3(128, 32), dim3(32, 8)>>>(lin1_w, p_W1, CC, 4*CC);
    tr_kernel<<<dim3(32, 128), dim3(32, 8)>>>(lin2_w, p_W2, 4*CC, CC);
    bias_pack_kernel<<<3, CC>>>(bq, bk, bv, p_bqkv);
    ln_kernel<<<ROWS_FULL, 256>>>(x, p_h, ln1_w, ln1_b);

    // KV: [8192, 2048] = h @ [Wk|Wv]^T, scatter to g_K/g_V
    tc_gemm<0,1><<<NPERS, 256, GEMM_SMEM>>>(
        p_h, p_Wqkv + CC*CC, nullptr, p_bqkv + CC, p_K, p_V,
        ROWS_FULL, 2*CC, CC);
    // Q: [4096, 1024] = h[last cut rows] @ Wq^T, scatter to g_Q
    tc_gemm<1,0><<<256, 256, GEMM_SMEM>>>(
        p_h, p_Wqkv, p_Q, p_bqkv, nullptr, nullptr,
        ROWS_CUT, CC, CC);

    // V transpose for PV mma
    vtr_kernel<<<dim3(TT/32, HS/32, BB*HH), dim3(32, 8)>>>(p_V, p_Vt);

    // attention (tensor cores)
    attn_tc<<<dim3(CUT/64, BB*HH), 128, ATT_SMEM>>>(p_Q, p_K, p_Vt, p_o);

    // proj + residual(x, last-cut rows) -> g_res
    tc_gemm<0,2><<<256, 256, GEMM_SMEM>>>(
        p_o, p_Wp, p_res, proj_b, x, nullptr, ROWS_CUT, CC, CC);

    // LN2
    ln_kernel<<<ROWS_CUT, 256>>>(p_res, p_h2, ln2_w, ln2_b);

    // MLP
    tc_gemm<0,3><<<NPERS, 256, GEMM_SMEM>>>(
        p_h2, p_W1, p_a1, lin1_b, nullptr, nullptr, ROWS_CUT, 4*CC, CC);
    tc_gemm<0,4><<<256, 256, GEMM_SMEM>>>(
        p_a1, p_W2, out, lin2_b, p_res, nullptr, ROWS_CUT, CC, 4*CC);
}

// round 12
// speedup vs baseline: 1.0839x; 1.0839x over previous
#include <cuda_runtime.h>
#include <cuda_bf16.h>
#include <cstdint>
#include <math.h>

// ---------------------------------------------------------------------------
// Problem constants
// ---------------------------------------------------------------------------
#define BB   4
#define TT   2048
#define CC   1024
#define HH   16
#define HS   64
#define CUT  1024
#define ROWS_FULL (BB*TT)   // 8192
#define ROWS_CUT  (BB*CUT)  // 4096
#define SCALE 0.03125f      // C^-0.5

// ---------------------------------------------------------------------------
// Scratch (device globals; no allocations allowed)
// ---------------------------------------------------------------------------
__device__ float g_h   [ROWS_FULL * CC];
__device__ float g_K   [BB*HH*TT*HS];
__device__ float g_Vt  [BB*HH*HS*TT];     // V transposed [bh][d][t]
__device__ float g_Q   [BB*HH*CUT*HS];
__device__ float g_o   [ROWS_CUT * CC];
__device__ float g_res [ROWS_CUT * CC];
__device__ float g_h2  [ROWS_CUT * CC];
__device__ float g_a1  [ROWS_CUT * 4*CC];
__device__ float g_Wqkv[3 * CC * CC];     // [3072, 1024] K-major
__device__ float g_Wp  [CC * CC];
__device__ float g_W1  [4*CC * CC];
__device__ float g_W2  [CC * 4*CC];
__device__ float g_bqkv[3 * CC];

// ---------------------------------------------------------------------------
// Helpers
// ---------------------------------------------------------------------------
__device__ __forceinline__ uint32_t smem_u32(const void* p) {
    uint32_t a;
    asm("{ .reg .u64 t; cvta.to.shared.u64 t, %1; cvt.u32.u64 %0, t; }"
        : "=r"(a) : "l"(p));
    return a;
}
// round fp32 -> tf32 (nearest) so HW tf32 truncation is a no-op
__device__ __forceinline__ float rtf32(float x) {
    uint32_t u = __float_as_uint(x);
    u = (u + 0x1000u) & 0xFFFFE000u;
    return __uint_as_float(u);
}
__device__ __forceinline__ float gelu_exact(float x) {
    return 0.5f * x * (1.0f + erff(x * 0.70710678118654752440f));
}

#define CP_ASYNC16(dst, src) \
    asm volatile("cp.async.cg.shared.global [%0], [%1], 16;" :: "r"(dst), "l"(src))
#define CP_COMMIT() asm volatile("cp.async.commit_group;")
#define CP_WAIT(n)  asm volatile("cp.async.wait_group %0;" :: "n"(n))

#define LDSM_X4(r0, r1, r2, r3, a) \
    asm volatile("ldmatrix.sync.aligned.m8n8.x4.shared.b16 {%0,%1,%2,%3}, [%4];" \
        : "=r"(r0), "=r"(r1), "=r"(r2), "=r"(r3) : "r"(a))

__device__ __forceinline__ void mma_tf32(float* c, const uint32_t* a, const uint32_t* b) {
    asm volatile(
        "mma.sync.aligned.m16n8k8.row.col.f32.tf32.tf32.f32 "
        "{%0,%1,%2,%3}, {%4,%5,%6,%7}, {%8,%9}, {%0,%1,%2,%3};"
        : "+f"(c[0]), "+f"(c[1]), "+f"(c[2]), "+f"(c[3])
        : "r"(a[0]), "r"(a[1]), "r"(a[2]), "r"(a[3]), "r"(b[0]), "r"(b[1]));
}

// ---------------------------------------------------------------------------
// Transpose + round: dst[n*K+k] = rtf32(src[k*N+n])
// ---------------------------------------------------------------------------
__global__ void tr_kernel(const float* __restrict__ src, float* __restrict__ dst,
                          int K, int N)
{
    __shared__ float t[32][33];
    int k0 = blockIdx.y * 32, n0 = blockIdx.x * 32;
    int tx = threadIdx.x, ty = threadIdx.y;      // 32 x 8
    #pragma unroll
    for (int i = 0; i < 32; i += 8)
        t[ty + i][tx] = src[(size_t)(k0 + ty + i) * N + n0 + tx];
    __syncthreads();
    #pragma unroll
    for (int i = 0; i < 32; i += 8)
        dst[(size_t)(n0 + ty + i) * K + k0 + tx] = rtf32(t[tx][ty + i]);
}

// QKV: [H,C,HS] x3 -> [3072, 1024] K-major; batch z: w=z/16, h=z%16
__global__ void qkv_tr_kernel(const float* __restrict__ Wq,
                              const float* __restrict__ Wk,
                              const float* __restrict__ Wv,
                              float* __restrict__ dst)
{
    __shared__ float t[32][33];
    int z = blockIdx.z, w = z >> 4, h = z & 15;
    const float* W = (w == 0) ? Wq : ((w == 1) ? Wk : Wv);
    const float* src = W + (size_t)h * CC * HS;
    float* d = dst + (size_t)w * CC * CC + (size_t)(h * HS) * CC;
    int k0 = blockIdx.y * 32, n0 = blockIdx.x * 32;
    int tx = threadIdx.x, ty = threadIdx.y;
    #pragma unroll
    for (int i = 0; i < 32; i += 8)
        t[ty + i][tx] = src[(size_t)(k0 + ty + i) * HS + n0 + tx];
    __syncthreads();
    #pragma unroll
    for (int i = 0; i < 32; i += 8)
        d[(size_t)(n0 + ty + i) * CC + k0 + tx] = rtf32(t[tx][ty + i]);
}

__global__ void bias_pack_kernel(const float* __restrict__ bq,
                                 const float* __restrict__ bk,
                                 const float* __restrict__ bv,
                                 float* __restrict__ out)
{
    int w = blockIdx.x, i = threadIdx.x;
    const float* b = (w == 0) ? bq : ((w == 1) ? bk : bv);
    out[w * CC + i] = b[i];
}

// ---------------------------------------------------------------------------
// LayerNorm (rounds output to tf32 — it only feeds GEMMs)
// ---------------------------------------------------------------------------
__global__ void ln_kernel(const float* __restrict__ in, float* __restrict__ out,
                          const float* __restrict__ w, const float* __restrict__ b)
{
    int row = blockIdx.x;
    int tid = threadIdx.x;
    const float4 x4 = ((const float4*)(in + (size_t)row * CC))[tid];
    float s  = x4.x + x4.y + x4.z + x4.w;
    float s2 = x4.x*x4.x + x4.y*x4.y + x4.z*x4.z + x4.w*x4.w;
    #pragma unroll
    for (int off = 16; off > 0; off >>= 1) {
        s  += __shfl_xor_sync(0xffffffffu, s,  off);
        s2 += __shfl_xor_sync(0xffffffffu, s2, off);
    }
    __shared__ float red[2][8];
    int wid = tid >> 5, lane = tid & 31;
    if (lane == 0) { red[0][wid] = s; red[1][wid] = s2; }
    __syncthreads();
    float ts = 0.f, ts2 = 0.f;
    #pragma unroll
    for (int i = 0; i < 8; i++) { ts += red[0][i]; ts2 += red[1][i]; }
    float mean = ts * (1.0f / CC);
    float var  = ts2 * (1.0f / CC) - mean * mean;
    float rstd = rsqrtf(var + 1e-5f);
    const float4 w4 = ((const float4*)w)[tid];
    const float4 b4 = ((const float4*)b)[tid];
    float4 o4;
    o4.x = rtf32((x4.x - mean) * rstd * w4.x + b4.x);
    o4.y = rtf32((x4.y - mean) * rstd * w4.y + b4.y);
    o4.z = rtf32((x4.z - mean) * rstd * w4.z + b4.z);
    o4.w = rtf32((x4.w - mean) * rstd * w4.w + b4.w);
    ((float4*)(out + (size_t)row * CC))[tid] = o4;
}

// ---------------------------------------------------------------------------
// Tensor-core tf32 GEMM via mma.sync (m16n8k8).
// CTA tile 128x128, BK=32, 256 threads: 8 warps 2(M)x4(N), warp tile 64x32.
// AMAP: 0 identity A rows, 1 = last-CUT rows of [B,T] layout
// EPI:  0 = Q scatter [b,h,s,d] (N=1024, tf32 round)
//       1 = KV scatter (N=2048: cols<1024 -> R1 = K [b,h,t,d];
//           cols>=1024 -> R2 = Vt [b,h,d,t] transposed; tf32 round)
//       2 = +x residual (row remap) -> C
//       3 = gelu+round -> C
//       4 = +R1 residual -> C
// ---------------------------------------------------------------------------
#define GEMM_SMEM (3 * 8192 * 4)   // 96 KB

template<int AMAP, int EPI>
__global__ void __launch_bounds__(256)
tc_gemm(const float* __restrict__ A, const float* __restrict__ Bt,
        float* __restrict__ C, const float* __restrict__ bias,
        const float* __restrict__ R1, const float* __restrict__ R2,
        int M, int N, int K)
{
    extern __shared__ float sm[];
    __shared__ float sbias[128];

    const int tid  = threadIdx.x;
    const int lane = tid & 31;
    const int warp = tid >> 5;
    const int wm   = warp & 1;
    const int wn   = warp >> 1;
    const int m0   = blockIdx.y * 128;
    const int n0   = blockIdx.x * 128;

    if (tid < 128) sbias[tid] = bias[n0 + tid];

    const uint32_t smb = smem_u32(sm);
    const int nt = K >> 5;

    auto load_tile = [&](int it) {
        const int s = it % 3;
        const uint32_t sa = smb + (uint32_t)s * 32768u;
        const uint32_t sb = sa + 16384u;
        const float* gA = A  + (size_t)it * 32;
        const float* gB = Bt + (size_t)it * 32;
        #pragma unroll
        for (int i = 0; i < 4; i++) {
            int lin = i * 256 + tid;
            int r = lin >> 3;
            int g = lin & 7;
            int row = m0 + r;
            int arow = AMAP ? ((row >> 10) * TT + (TT - CUT) + (row & (CUT-1)))
                            : row;
            uint32_t off = (uint32_t)(r * 32 + ((g ^ (r & 7)) * 4)) * 4u;
            CP_ASYNC16(sa + off, gA + (size_t)arow * K + g * 4);
            CP_ASYNC16(sb + off, gB + (size_t)(n0 + r) * K + g * 4);
        }
        CP_COMMIT();
    };

    float acc[4][4][4];
    #pragma unroll
    for (int i = 0; i < 4; i++)
        #pragma unroll
        for (int j = 0; j < 4; j++)
            #pragma unroll
            for (int k = 0; k < 4; k++) acc[i][j][k] = 0.f;

    int rA[4], rB[2];
    #pragma unroll
    for (int mf = 0; mf < 4; mf++) rA[mf] = wm * 64 + mf * 16 + (lane & 15);
    #pragma unroll
    for (int p = 0; p < 2; p++)
        rB[p] = wn * 32 + p * 16 + (lane & 7) + ((lane >> 4) << 3);
    const int gA_hi = lane >> 4;
    const int gB_hi = (lane >> 3) & 1;

    load_tile(0);
    if (nt > 1) load_tile(1);

    for (int it = 0; it < nt; ++it) {
        const int s = it % 3;
        if (it < nt - 1) { CP_WAIT(1); } else { CP_WAIT(0); }
        __syncthreads();
        if (it + 2 < nt) load_tile(it + 2);

        const uint32_t sa = smb + (uint32_t)s * 32768u;
        const uint32_t sb = sa + 16384u;

        #pragma unroll
        for (int ks = 0; ks < 4; ks++) {
            uint32_t a[4][4], b[4][2];
            #pragma unroll
            for (int mf = 0; mf < 4; mf++) {
                int g = (2 * ks + gA_hi) ^ (rA[mf] & 7);
                uint32_t addr = sa + (uint32_t)(rA[mf] * 32 + g * 4) * 4u;
                LDSM_X4(a[mf][0], a[mf][1], a[mf][2], a[mf][3], addr);
            }
            #pragma unroll
            for (int p = 0; p < 2; p++) {
                int g = (2 * ks + gB_hi) ^ (rB[p] & 7);
                uint32_t addr = sb + (uint32_t)(rB[p] * 32 + g * 4) * 4u;
                LDSM_X4(b[2*p][0], b[2*p][1], b[2*p+1][0], b[2*p+1][1], addr);
            }
            #pragma unroll
            for (int mf = 0; mf < 4; mf++)
                #pragma unroll
                for (int nf = 0; nf < 4; nf++)
                    mma_tf32(acc[mf][nf], a[mf], b[nf]);
        }
    }

    // ---- epilogue ----
    #pragma unroll
    for (int mf = 0; mf < 4; mf++) {
        #pragma unroll
        for (int nf = 0; nf < 4; nf++) {
            int lrow = wm * 64 + mf * 16 + (lane >> 2);
            int lcol = wn * 32 + nf * 8 + 2 * (lane & 3);
            float sb0 = sbias[lcol], sb1 = sbias[lcol + 1];
            #pragma unroll
            for (int rr = 0; rr < 2; rr++) {
                int gi   = m0 + lrow + rr * 8;
                int gcol = n0 + lcol;
                float2 v = make_float2(acc[mf][nf][2*rr]   + sb0,
                                       acc[mf][nf][2*rr+1] + sb1);
                if (EPI == 0) {
                    v.x = rtf32(v.x); v.y = rtf32(v.y);
                    int h = gcol >> 6, d0 = gcol & 63;
                    int b_ = gi >> 10, s_ = gi & 1023;
                    *(float2*)(C + ((((size_t)b_ * HH + h) * CUT) + s_) * HS + d0) = v;
                } else if (EPI == 1) {
                    v.x = rtf32(v.x); v.y = rtf32(v.y);
                    int w = gcol >> 10, r = gcol & 1023;
                    int h = r >> 6, d0 = r & 63;
                    int b_ = gi >> 11, t = gi & 2047;
                    if (w == 0) {
                        *(float2*)((float*)R1 + (((size_t)b_ * HH + h) * TT + t) * HS + d0) = v;
                    } else {
                        // V transposed: Vt[bh][d][t]
                        float* vt = (float*)R2 + (((size_t)b_ * HH + h) * HS) * TT;
                        vt[(size_t)d0 * TT + t]       = v.x;
                        vt[(size_t)(d0 + 1) * TT + t] = v.y;
                    }
                } else if (EPI == 2) {
                    int xrow = (gi >> 10) * TT + (TT - CUT) + (gi & 1023);
                    float2 xv = *(const float2*)(R1 + (size_t)xrow * CC + gcol);
                    *(float2*)(C + (size_t)gi * N + gcol) =
                        make_float2(v.x + xv.x, v.y + xv.y);
                } else if (EPI == 3) {
                    *(float2*)(C + (size_t)gi * N + gcol) =
                        make_float2(rtf32(gelu_exact(v.x)), rtf32(gelu_exact(v.y)));
                } else {
                    float2 rv = *(const float2*)(R1 + (size_t)gi * N + gcol);
                    *(float2*)(C + (size_t)gi * N + gcol) =
                        make_float2(v.x + rv.x, v.y + rv.y);
                }
            }
        }
    }
}

// ---------------------------------------------------------------------------
// Tensor-core flash attention (tf32 mma for QK^T and PV).
// Grid (qt=16, bh=64), 128 threads (4 warps x 16 query rows).
// SMEM floats: QsPs[4096] | Ks[2][4096] | Vs[2][4096]  = 80KB
// ---------------------------------------------------------------------------
#define ATT_SMEM (20480 * 4)

__global__ void __launch_bounds__(128)
attn_tc(const float* __restrict__ Qg, const float* __restrict__ Kg,
        const float* __restrict__ Vtg, float* __restrict__ O)
{
    extern __shared__ float smf[];
    const int qt   = blockIdx.x;
    const int bh   = blockIdx.y;
    const int tid  = threadIdx.x;
    const int lane = tid & 31;
    const int warp = tid >> 5;
    const uint32_t sb = smem_u32(smf);
    const uint32_t sQP = sb;

    const float* Qbase = Qg  + ((size_t)bh * CUT + (size_t)qt * 64) * HS;
    const float* Kbase = Kg  + (size_t)bh * TT * HS;
    const float* Vbase = Vtg + (size_t)bh * HS * TT;

    auto swb = [](int r, int g) {
        return (uint32_t)(r * 64 + ((g ^ (r & 7)) * 4)) * 4u;
    };

    #pragma unroll
    for (int it = 0; it < 8; it++) {
        int lin = it * 128 + tid;
        int r = lin >> 4, g = lin & 15;
        CP_ASYNC16(sQP + swb(r, g), Qbase + r * 64 + g * 4);
    }
    CP_COMMIT();

    auto load_kv = [&](int kt, int buf) {
        uint32_t kdst = sb + (uint32_t)(4096 + buf * 4096) * 4u;
        uint32_t vdst = sb + (uint32_t)(12288 + buf * 4096) * 4u;
        const float* ks = Kbase + (size_t)kt * 64 * 64;
        const float* vs = Vbase + (size_t)kt * 64;
        #pragma unroll
        for (int it = 0; it < 8; it++) {
            int lin = it * 128 + tid;
            int r = lin >> 4, g = lin & 15;
            CP_ASYNC16(kdst + swb(r, g), ks + (size_t)r * 64 + g * 4);
            CP_ASYNC16(vdst + swb(r, g), vs + (size_t)r * TT + g * 4);
        }
        CP_COMMIT();
    };

    load_kv(0, 0);
    CP_WAIT(1);
    __syncthreads();

    uint32_t qf[8][4];
    {
        int rA = warp * 16 + (lane & 15);
        #pragma unroll
        for (int ks = 0; ks < 8; ks++) {
            int g = (2 * ks + (lane >> 4)) ^ (rA & 7);
            uint32_t addr = sQP + (uint32_t)(rA * 64 + g * 4) * 4u;
            LDSM_X4(qf[ks][0], qf[ks][1], qf[ks][2], qf[ks][3], addr);
        }
    }

    float m[2] = {-1e30f, -1e30f}, l[2] = {0.f, 0.f};
    float oacc[8][4];
    #pragma unroll
    for (int nf = 0; nf < 8; nf++)
        #pragma unroll
        for (int e = 0; e < 4; e++) oacc[nf][e] = 0.f;

    const int rA_ld  = warp * 16 + (lane & 15);
    const int gA_hi  = lane >> 4;
    const int gB_hi  = (lane >> 3) & 1;
    int rB[4];
    #pragma unroll
    for (int p = 0; p < 4; p++)
        rB[p] = p * 16 + (lane & 7) + ((lane >> 4) << 3);

    const int ktmax = (TT - CUT) / 64 + qt;

    for (int kt = 0; kt <= ktmax; kt++) {
        const int buf = kt & 1;
        __syncthreads();
        if (kt < ktmax) load_kv(kt + 1, buf ^ 1);
        if (kt < ktmax) { CP_WAIT(1); } else { CP_WAIT(0); }
        __syncthreads();

        const uint32_t kB = sb + (uint32_t)(4096 + buf * 4096) * 4u;
        const uint32_t vB = sb + (uint32_t)(12288 + buf * 4096) * 4u;

        float sfr[8][4];
        #pragma unroll
        for (int nf = 0; nf < 8; nf++)
            #pragma unroll
            for (int e = 0; e < 4; e++) sfr[nf][e] = 0.f;

        #pragma unroll
        for (int ks = 0; ks < 8; ks++) {
            uint32_t b[8][2];
            #pragma unroll
            for (int p = 0; p < 4; p++) {
                int g = (2 * ks + gB_hi) ^ (rB[p] & 7);
                uint32_t addr = kB + (uint32_t)(rB[p] * 64 + g * 4) * 4u;
                LDSM_X4(b[2*p][0], b[2*p][1], b[2*p+1][0], b[2*p+1][1], addr);
            }
            #pragma unroll
            for (int nf = 0; nf < 8; nf++)
                mma_tf32(sfr[nf], qf[ks], b[nf]);
        }

        #pragma unroll
        for (int nf = 0; nf < 8; nf++)
            #pragma unroll
            for (int e = 0; e < 4; e++) sfr[nf][e] *= SCALE;

        if (kt == ktmax) {
            int r0 = warp * 16 + (lane >> 2);
            #pragma unroll
            for (int nf = 0; nf < 8; nf++) {
                int c0 = nf * 8 + 2 * (lane & 3);
                if (c0     > r0)     sfr[nf][0] = -1e30f;
                if (c0 + 1 > r0)     sfr[nf][1] = -1e30f;
                if (c0     > r0 + 8) sfr[nf][2] = -1e30f;
                if (c0 + 1 > r0 + 8) sfr[nf][3] = -1e30f;
            }
        }

        float mt[2] = {-1e30f, -1e30f};
        #pragma unroll
        for (int nf = 0; nf < 8; nf++) {
            mt[0] = fmaxf(mt[0], fmaxf(sfr[nf][0], sfr[nf][1]));
            mt[1] = fmaxf(mt[1], fmaxf(sfr[nf][2], sfr[nf][3]));
        }
        #pragma unroll
        for (int i = 0; i < 2; i++) {
            mt[i] = fmaxf(mt[i], __shfl_xor_sync(0xffffffffu, mt[i], 1));
            mt[i] = fmaxf(mt[i], __shfl_xor_sync(0xffffffffu, mt[i], 2));
        }
        float sc[2], rs[2];
        #pragma unroll
        for (int i = 0; i < 2; i++) {
            float mnew = fmaxf(m[i], mt[i]);
            sc[i] = __expf(m[i] - mnew);
            m[i]  = mnew;
            rs[i] = 0.f;
        }
        #pragma unroll
        for (int nf = 0; nf < 8; nf++) {
            sfr[nf][0] = __expf(sfr[nf][0] - m[0]);
            sfr[nf][1] = __expf(sfr[nf][1] - m[0]);
            sfr[nf][2] = __expf(sfr[nf][2] - m[1]);
            sfr[nf][3] = __expf(sfr[nf][3] - m[1]);
            rs[0] += sfr[nf][0] + sfr[nf][1];
            rs[1] += sfr[nf][2] + sfr[nf][3];
        }
        #pragma unroll
        for (int i = 0; i < 2; i++) {
            rs[i] += __shfl_xor_sync(0xffffffffu, rs[i], 1);
            rs[i] += __shfl_xor_sync(0xffffffffu, rs[i], 2);
            l[i] = l[i] * sc[i] + rs[i];
        }
        #pragma unroll
        for (int nf = 0; nf < 8; nf++) {
            oacc[nf][0] *= sc[0]; oacc[nf][1] *= sc[0];
            oacc[nf][2] *= sc[1]; oacc[nf][3] *= sc[1];
        }

        {
            int r0 = warp * 16 + (lane >> 2);
            #pragma unroll
            for (int nf = 0; nf < 8; nf++) {
                int j0 = nf * 8 + 2 * (lane & 3);
                int g = j0 >> 2, o4 = j0 & 3;
                int i1 = r0 * 64 + ((g ^ (r0 & 7)) * 4 + o4);
                int r2 = r0 + 8;
                int i2 = r2 * 64 + ((g ^ (r2 & 7)) * 4 + o4);
                *(float2*)(smf + i1) = make_float2(rtf32(sfr[nf][0]), rtf32(sfr[nf][1]));
                *(float2*)(smf + i2) = make_float2(rtf32(sfr[nf][2]), rtf32(sfr[nf][3]));
            }
        }
        __syncthreads();

        #pragma unroll
        for (int ks = 0; ks < 8; ks++) {
            uint32_t a[4];
            {
                int g = (2 * ks + gA_hi) ^ (rA_ld & 7);
                uint32_t addr = sQP + (uint32_t)(rA_ld * 64 + g * 4) * 4u;
                LDSM_X4(a[0], a[1], a[2], a[3], addr);
            }
            uint32_t b[8][2];
            #pragma unroll
            for (int p = 0; p < 4; p++) {
                int g = (2 * ks + gB_hi) ^ (rB[p] & 7);
                uint32_t addr = vB + (uint32_t)(rB[p] * 64 + g * 4) * 4u;
                LDSM_X4(b[2*p][0], b[2*p][1], b[2*p+1][0], b[2*p+1][1], addr);
            }
            #pragma unroll
            for (int nf = 0; nf < 8; nf++)
                mma_tf32(oacc[nf], a, b[nf]);
        }
    }

    const int b_ = bh >> 4, h_ = bh & 15;
    const int r0 = warp * 16 + (lane >> 2);
    float inv0 = 1.0f / l[0], inv1 = 1.0f / l[1];
    #pragma unroll
    for (int nf = 0; nf < 8; nf++) {
        int j0 = nf * 8 + 2 * (lane & 3);
        size_t a1 = ((size_t)b_ * CUT + qt * 64 + r0) * CC + h_ * HS + j0;
        size_t a2 = ((size_t)b_ * CUT + qt * 64 + r0 + 8) * CC + h_ * HS + j0;
        *(float2*)(O + a1) = make_float2(rtf32(oacc[nf][0] * inv0),
                                         rtf32(oacc[nf][1] * inv0));
        *(float2*)(O + a2) = make_float2(rtf32(oacc[nf][2] * inv1),
                                         rtf32(oacc[nf][3] * inv1));
    }
}

// ---------------------------------------------------------------------------
// Launch
// ---------------------------------------------------------------------------
extern "C" void kernel_launch(void* const* d_in, const int* in_sizes, int n_in,
                              void* d_out, int out_size)
{
    const float* x      = (const float*)d_in[0];
    const float* ln1_w  = (const float*)d_in[1];
    const float* ln1_b  = (const float*)d_in[2];
    const float* Wq     = (const float*)d_in[3];
    const float* bq     = (const float*)d_in[4];
    const float* Wk     = (const float*)d_in[5];
    const float* bk     = (const float*)d_in[6];
    const float* Wv     = (const float*)d_in[7];
    const float* bv     = (const float*)d_in[8];
    const float* proj_w = (const float*)d_in[9];
    const float* proj_b = (const float*)d_in[10];
    const float* ln2_w  = (const float*)d_in[11];
    const float* ln2_b  = (const float*)d_in[12];
    const float* lin1_w = (const float*)d_in[13];
    const float* lin1_b = (const float*)d_in[14];
    const float* lin2_w = (const float*)d_in[15];
    const float* lin2_b = (const float*)d_in[16];
    float* out = (float*)d_out;

    float *p_h, *p_K, *p_Vt, *p_Q, *p_o, *p_res, *p_h2, *p_a1;
    float *p_Wqkv, *p_Wp, *p_W1, *p_W2, *p_bqkv;
    cudaGetSymbolAddress((void**)&p_h,    g_h);
    cudaGetSymbolAddress((void**)&p_K,    g_K);
    cudaGetSymbolAddress((void**)&p_Vt,   g_Vt);
    cudaGetSymbolAddress((void**)&p_Q,    g_Q);
    cudaGetSymbolAddress((void**)&p_o,    g_o);
    cudaGetSymbolAddress((void**)&p_res,  g_res);
    cudaGetSymbolAddress((void**)&p_h2,   g_h2);
    cudaGetSymbolAddress((void**)&p_a1,   g_a1);
    cudaGetSymbolAddress((void**)&p_Wqkv, g_Wqkv);
    cudaGetSymbolAddress((void**)&p_Wp,   g_Wp);
    cudaGetSymbolAddress((void**)&p_W1,   g_W1);
    cudaGetSymbolAddress((void**)&p_W2,   g_W2);
    cudaGetSymbolAddress((void**)&p_bqkv, g_bqkv);

    static bool once = false;
    if (!once) {
        cudaFuncSetAttribute(attn_tc,
                             cudaFuncAttributeMaxDynamicSharedMemorySize, ATT_SMEM);
        cudaFuncSetAttribute((const void*)tc_gemm<1,0>,
                             cudaFuncAttributeMaxDynamicSharedMemorySize, GEMM_SMEM);
        cudaFuncSetAttribute((const void*)tc_gemm<0,1>,
                             cudaFuncAttributeMaxDynamicSharedMemorySize, GEMM_SMEM);
        cudaFuncSetAttribute((const void*)tc_gemm<0,2>,
                             cudaFuncAttributeMaxDynamicSharedMemorySize, GEMM_SMEM);
        cudaFuncSetAttribute((const void*)tc_gemm<0,3>,
                             cudaFuncAttributeMaxDynamicSharedMemorySize, GEMM_SMEM);
        cudaFuncSetAttribute((const void*)tc_gemm<0,4>,
                             cudaFuncAttributeMaxDynamicSharedMemorySize, GEMM_SMEM);
        once = true;
    }

    // weight repack (transpose + tf32 round) + bias pack + LN1
    qkv_tr_kernel<<<dim3(2, 32, 48), dim3(32, 8)>>>(Wq, Wk, Wv, p_Wqkv);
    tr_kernel<<<dim3(32, 32),  dim3(32, 8)>>>(proj_w, p_Wp, CC, CC);
    tr_kernel<<<dim3(128, 32), dim3(32, 8)>>>(lin1_w, p_W1, CC, 4*CC);
    tr_kernel<<<dim3(32, 128), dim3(32, 8)>>>(lin2_w, p_W2, 4*CC, CC);
    bias_pack_kernel<<<3, CC>>>(bq, bk, bv, p_bqkv);
    ln_kernel<<<ROWS_FULL, 256>>>(x, p_h, ln1_w, ln1_b);

    // KV: [8192, 2048] = h @ [Wk|Wv]^T -> K (natural), Vt (transposed)
    tc_gemm<0,1><<<dim3(2*CC/128, ROWS_FULL/128), 256, GEMM_SMEM>>>(
        p_h, p_Wqkv + CC*CC, nullptr, p_bqkv + CC, p_K, p_Vt,
        ROWS_FULL, 2*CC, CC);
    // Q: [4096, 1024] = h[last cut rows] @ Wq^T -> g_Q
    tc_gemm<1,0><<<dim3(CC/128, ROWS_CUT/128), 256, GEMM_SMEM>>>(
        p_h, p_Wqkv, p_Q, p_bqkv, nullptr, nullptr,
        ROWS_CUT, CC, CC);

    // attention (tensor cores)
    attn_tc<<<dim3(CUT/64, BB*HH), 128, ATT_SMEM>>>(p_Q, p_K, p_Vt, p_o);

    // proj + residual(x, last-cut rows) -> g_res
    tc_gemm<0,2><<<dim3(CC/128, ROWS_CUT/128), 256, GEMM_SMEM>>>(
        p_o, p_Wp, p_res, proj_b, x, nullptr, ROWS_CUT, CC, CC);

    // LN2
    ln_kernel<<<ROWS_CUT, 256>>>(p_res, p_h2, ln2_w, ln2_b);

    // MLP
    tc_gemm<0,3><<<dim3(4*CC/128, ROWS_CUT/128), 256, GEMM_SMEM>>>(
        p_h2, p_W1, p_a1, lin1_b, nullptr, nullptr, ROWS_CUT, 4*CC, CC);
    tc_gemm<0,4><<<dim3(CC/128, ROWS_CUT/128), 256, GEMM_SMEM>>>(
        p_a1, p_W2, out, lin2_b, p_res, nullptr, ROWS_CUT, CC, 4*CC);
}